// round 12
// baseline (speedup 1.0000x reference)
#include <cuda_runtime.h>
#include <cuda_bf16.h>

// bow_labeler: masked mean-pool over L, then 14 small linear heads (54 outputs).
// B=256, L=512, D=768.
// SINGLE kernel, 2304 blocks x 192 threads:
//   blocks [0, 2048): streamers — masked partial column sums for one
//       (batch, 64-row chunk); publish via fence + per-batch counter.
//   blocks [2048, 2304): one epilogue block per batch — spins until its
//       batch's 8 partials are published (early batches complete while later
//       ones still stream), then reduce + normalize + 54-head GEMV.
// Counters self-reset for graph replay.

#define B_DIM   256
#define L_DIM   512
#define D_DIM   768
#define N_OUT   54
#define SPLIT   8
#define L_CHUNK (L_DIM / SPLIT)   // 64
#define D4      (D_DIM / 4)       // 192 float4 per row
#define NT      192
#define NSTREAM (B_DIM * SPLIT)   // 2048

__device__ float g_partial[B_DIM * SPLIT * D_DIM];   // 6 MB
__device__ int   g_done[B_DIM];                      // zero-init; self-reset

__device__ __forceinline__ void f4acc(float4& a, const float4& v) {
    a.x += v.x; a.y += v.y; a.z += v.z; a.w += v.w;
}

__global__ __launch_bounds__(NT) void bow_pipelined_kernel(
    const float* __restrict__ fh,
    const int*   __restrict__ mask,
    const float* __restrict__ W13,
    const float* __restrict__ b13,
    const float* __restrict__ W14,
    const float* __restrict__ b14,
    float*       __restrict__ out)
{
    const int bid  = blockIdx.x;
    const int tid  = threadIdx.x;
    const int lane = tid & 31;
    const int warp = tid >> 5;

    if (bid < NSTREAM) {
        // ================= streamer =================
        const int s = bid & (SPLIT - 1);
        const int b = bid >> 3;

        __shared__ int s_mask[L_CHUNK];
        if (tid < L_CHUNK) s_mask[tid] = mask[b * L_DIM + s * L_CHUNK + tid];
        __syncthreads();

        const float4* base =
            (const float4*)(fh + ((size_t)b * L_DIM + (size_t)s * L_CHUNK) * D_DIM) + tid;

        float4 a0 = make_float4(0.f,0.f,0.f,0.f);
        float4 a1 = make_float4(0.f,0.f,0.f,0.f);
        float4 a2 = make_float4(0.f,0.f,0.f,0.f);
        float4 a3 = make_float4(0.f,0.f,0.f,0.f);
        #pragma unroll 1
        for (int l = 0; l < L_CHUNK; l += 8) {
            if (s_mask[l+0]) f4acc(a0, base[(size_t)(l+0) * D4]);
            if (s_mask[l+1]) f4acc(a1, base[(size_t)(l+1) * D4]);
            if (s_mask[l+2]) f4acc(a2, base[(size_t)(l+2) * D4]);
            if (s_mask[l+3]) f4acc(a3, base[(size_t)(l+3) * D4]);
            if (s_mask[l+4]) f4acc(a0, base[(size_t)(l+4) * D4]);
            if (s_mask[l+5]) f4acc(a1, base[(size_t)(l+5) * D4]);
            if (s_mask[l+6]) f4acc(a2, base[(size_t)(l+6) * D4]);
            if (s_mask[l+7]) f4acc(a3, base[(size_t)(l+7) * D4]);
        }
        f4acc(a0, a1); f4acc(a2, a3); f4acc(a0, a2);

        ((float4*)(g_partial + ((size_t)b * SPLIT + s) * D_DIM))[tid] = a0;

        // Publish: stores visible device-wide, then bump arrival counter.
        __threadfence();
        __syncthreads();
        if (tid == 0) atomicAdd(&g_done[b], 1);
        return;
    }

    // ================= epilogue (one block per batch) =================
    const int b = bid - NSTREAM;

    __shared__ float4 s_pooled[D4];   // 3 KB
    __shared__ int    s_cnt;
    __shared__ float  s_inv;

    if (tid == 0) s_cnt = 0;
    __syncthreads();

    // Work independent of the partials: valid-token count (overlaps the spin).
    {
        const int* mrow = mask + b * L_DIM;
        int m = mrow[tid] + mrow[tid + 192] + ((tid < 128) ? mrow[tid + 384] : 0);
        #pragma unroll
        for (int off = 16; off; off >>= 1)
            m += __shfl_down_sync(0xffffffffu, m, off);
        if (lane == 0) atomicAdd(&s_cnt, m);
    }

    // Spin until all 8 streamer blocks for this batch have published.
    if (tid == 0) {
        volatile int* dp = &g_done[b];
        while (*dp < SPLIT) __nanosleep(200);
        g_done[b] = 0;                 // reset for next graph replay
        s_inv = 1.0f / (float)s_cnt;
    }
    __syncthreads();
    __threadfence();                   // acquire before reading partials

    // Reduce the 8 partials for this thread's float4 column (L2-coherent).
    const float4* gp4 = (const float4*)(g_partial + (size_t)b * SPLIT * D_DIM);
    float4 cs = make_float4(0.f,0.f,0.f,0.f);
    #pragma unroll
    for (int s2 = 0; s2 < SPLIT; s2++)
        cs = make_float4(cs.x, cs.y, cs.z, cs.w), f4acc(cs, __ldcg(&gp4[(size_t)s2 * D4 + tid]));

    {
        float inv = s_inv;
        cs.x *= inv; cs.y *= inv; cs.z *= inv; cs.w *= inv;
        s_pooled[tid] = cs;
    }
    __syncthreads();

    // 54 dot-products of length 768 over 6 warps (9 outputs each).
    for (int o = warp; o < N_OUT; o += (NT / 32)) {
        const float4* w4 = (const float4*)((o < 52) ? (W13 + (size_t)o * D_DIM)
                                                    : (W14 + (size_t)(o - 52) * D_DIM));
        const float bias = (o < 52) ? b13[o] : b14[o - 52];
        float acc = 0.f;
        #pragma unroll
        for (int i = 0; i < D4 / 32; i++) {
            float4 w = w4[lane + 32 * i];
            float4 p = s_pooled[lane + 32 * i];
            acc += w.x * p.x + w.y * p.y + w.z * p.z + w.w * p.w;
        }
        #pragma unroll
        for (int off = 16; off; off >>= 1)
            acc += __shfl_down_sync(0xffffffffu, acc, off);
        if (lane == 0) out[b * N_OUT + o] = acc + bias;
    }
}

extern "C" void kernel_launch(void* const* d_in, const int* in_sizes, int n_in,
                              void* d_out, int out_size)
{
    const float* fh   = (const float*)d_in[0];
    const int*   mask = (const int*)d_in[1];
    const float* W13  = (const float*)d_in[2];
    const float* b13  = (const float*)d_in[3];
    const float* W14  = (const float*)d_in[4];
    const float* b14  = (const float*)d_in[5];
    float* out = (float*)d_out;

    bow_pipelined_kernel<<<NSTREAM + B_DIM, NT>>>(fh, mask, W13, b13, W14, b14, out);
}